// round 3
// baseline (speedup 1.0000x reference)
#include <cuda_runtime.h>
#include <math.h>
#include <stdint.h>

#define NN 50000
#define EE 800000
#define IN_DIM 128
#define HID 128
#define OUT_DIM 40
#define KHOP 10
#define AH 64
#define ALPHA 0.1f
#define EPS 1e-5f

// ----------------------------------------------------------------------------
// Static device scratch (no allocations allowed; referenced ONLY in device code)
// ----------------------------------------------------------------------------
__device__ float g_xs[(KHOP + 1) * (size_t)NN * HID];   // 281.6 MB: h at every hop
__device__ float g_h1[(size_t)NN * HID];                 // stem layer-1 output
__device__ float g_wsum[NN];
__device__ int   g_deg[NN];
__device__ int   g_rowptr[NN + 1];
__device__ int   g_cursor[NN];
__device__ float2 g_edge[EE];                            // {src as int bits, enorm} CSR by dest
__device__ float g_attw[(size_t)NN * (KHOP + 1)];

// transposed weights + folded BN constants
__device__ float g_Wt1[IN_DIM * HID];    // [k][n]
__device__ float g_Wt2[HID * HID];       // [k][n]
__device__ float g_attWt1[2 * HID * AH]; // [c][o]
__device__ float g_h1Wt[HID * (HID / 2)];// [c][o]  128x64
__device__ float g_h2Wt[(HID / 2) * OUT_DIM]; // [c][o] 64x40
__device__ float g_A1[HID], g_C1[HID], g_A2[HID], g_C2[HID], g_A3[HID / 2], g_C3[HID / 2];

// ----------------------------------------------------------------------------
// Prep: zero accumulators, transpose weights, fold BN
// ----------------------------------------------------------------------------
__global__ void zero_kernel() {
    int i = blockIdx.x * blockDim.x + threadIdx.x;
    if (i < NN) { g_wsum[i] = 0.f; g_deg[i] = 0; g_cursor[i] = 0; }
}

__global__ void prep_kernel(const float* __restrict__ lin1_w, const float* __restrict__ lin1_b,
                            const float* __restrict__ bn1_g, const float* __restrict__ bn1_b,
                            const float* __restrict__ bn1_m, const float* __restrict__ bn1_v,
                            const float* __restrict__ lin2_w, const float* __restrict__ lin2_b,
                            const float* __restrict__ bn2_g, const float* __restrict__ bn2_b,
                            const float* __restrict__ bn2_m, const float* __restrict__ bn2_v,
                            const float* __restrict__ att1_w,
                            const float* __restrict__ head1_w, const float* __restrict__ head1_b,
                            const float* __restrict__ bn3_g, const float* __restrict__ bn3_b,
                            const float* __restrict__ bn3_m, const float* __restrict__ bn3_v,
                            const float* __restrict__ head2_w) {
    int tid = blockIdx.x * blockDim.x + threadIdx.x;
    if (tid < IN_DIM * HID) {           // Wt1[k*128+n] = lin1_w[n*128+k]
        int k = tid >> 7, n = tid & 127;
        g_Wt1[tid] = lin1_w[n * IN_DIM + k];
        g_Wt2[tid] = lin2_w[n * HID + k];
    }
    if (tid < 2 * HID * AH) {           // attWt1[c*64+o] = att1_w[o*256+c]
        int c = tid >> 6, o = tid & 63;
        g_attWt1[tid] = att1_w[o * (2 * HID) + c];
    }
    if (tid < HID * (HID / 2)) {        // h1Wt[c*64+o] = head1_w[o*128+c]
        int c = tid >> 6, o = tid & 63;
        g_h1Wt[tid] = head1_w[o * HID + c];
    }
    if (tid < (HID / 2) * OUT_DIM) {    // h2Wt[c*40+o] = head2_w[o*64+c]
        int c = tid / OUT_DIM, o = tid % OUT_DIM;
        g_h2Wt[tid] = head2_w[o * (HID / 2) + c];
    }
    if (tid < HID) {
        float a1 = bn1_g[tid] * rsqrtf(bn1_v[tid] + EPS);
        g_A1[tid] = a1;
        g_C1[tid] = lin1_b[tid] * a1 + bn1_b[tid] - bn1_m[tid] * a1;
        float a2 = bn2_g[tid] * rsqrtf(bn2_v[tid] + EPS);
        g_A2[tid] = a2;
        g_C2[tid] = lin2_b[tid] * a2 + bn2_b[tid] - bn2_m[tid] * a2;
    }
    if (tid < HID / 2) {
        float a3 = bn3_g[tid] * rsqrtf(bn3_v[tid] + EPS);
        g_A3[tid] = a3;
        g_C3[tid] = head1_b[tid] * a3 + bn3_b[tid] - bn3_m[tid] * a3;
    }
}

// ----------------------------------------------------------------------------
// Graph preprocessing: wsum + degree histogram, scan, CSR fill
// edge_index is int32 [2, E] (JAX x64 disabled downcasts int64 -> int32)
// ----------------------------------------------------------------------------
__global__ void count_kernel(const int* __restrict__ ei, const float* __restrict__ ew) {
    int e = blockIdx.x * blockDim.x + threadIdx.x;
    if (e >= EE) return;
    int row = ei[e];
    int col = ei[EE + e];
    atomicAdd(&g_wsum[row], ew[e]);
    atomicAdd(&g_deg[col], 1);
}

__global__ void scan_kernel() {
    __shared__ int sh[1024];
    int t = threadIdx.x;
    const int CH = (NN + 1023) / 1024;
    int start = t * CH;
    int end = min(start + CH, NN);
    int s = 0;
    for (int i = start; i < end; ++i) s += g_deg[i];
    sh[t] = s;
    __syncthreads();
    for (int off = 1; off < 1024; off <<= 1) {
        int v = (t >= off) ? sh[t - off] : 0;
        __syncthreads();
        sh[t] += v;
        __syncthreads();
    }
    int run = sh[t] - s;  // exclusive prefix
    for (int i = start; i < end; ++i) { g_rowptr[i] = run; run += g_deg[i]; }
    if (end == NN) g_rowptr[NN] = run;
}

__global__ void fill_kernel(const int* __restrict__ ei, const float* __restrict__ ew) {
    int e = blockIdx.x * blockDim.x + threadIdx.x;
    if (e >= EE) return;
    int row = ei[e];
    int col = ei[EE + e];
    float en = ew[e] / fmaxf(g_wsum[row], 1.0f);
    int pos = g_rowptr[col] + atomicAdd(&g_cursor[col], 1);
    g_edge[pos] = make_float2(__int_as_float(row), en);
}

// ----------------------------------------------------------------------------
// Stem SGEMM: Y = act((X @ Wt) * A + C) [+ X residual]; 128x128 tile, 8x8/thread
// LAYER 0: X=x (ext), W=g_Wt1, out=g_h1. LAYER 1: X=g_h1, W=g_Wt2, out=g_xs[0] (+res)
// ----------------------------------------------------------------------------
template <int LAYER>
__global__ void gemm128_kernel(const float* __restrict__ Xext) {
    const float* __restrict__ X  = (LAYER == 0) ? Xext : g_h1;
    const float* __restrict__ Wt = (LAYER == 0) ? g_Wt1 : g_Wt2;
    const float* __restrict__ A  = (LAYER == 0) ? g_A1 : g_A2;
    const float* __restrict__ C  = (LAYER == 0) ? g_C1 : g_C2;
    float* __restrict__ Y        = (LAYER == 0) ? g_h1 : g_xs;

    __shared__ float As[8][128];
    __shared__ float Bs[8][128];
    int tid = threadIdx.x;
    int m0 = blockIdx.x * 128;
    int ty = tid >> 4, tx = tid & 15;
    float acc[8][8];
#pragma unroll
    for (int i = 0; i < 8; ++i)
#pragma unroll
        for (int j = 0; j < 8; ++j) acc[i][j] = 0.f;

    int lr = tid >> 1;            // row within tile for A load
    int lq = (tid & 1) * 4;       // k sub-offset
    int bkr = tid >> 5;           // k row for B load
    int bnc = (tid & 31) * 4;     // n offset

    for (int kc = 0; kc < 128; kc += 8) {
        float4 av = make_float4(0.f, 0.f, 0.f, 0.f);
        int gm = m0 + lr;
        if (gm < NN) av = *(const float4*)(X + (size_t)gm * 128 + kc + lq);
        As[lq + 0][lr] = av.x; As[lq + 1][lr] = av.y;
        As[lq + 2][lr] = av.z; As[lq + 3][lr] = av.w;
        *(float4*)&Bs[bkr][bnc] = *(const float4*)(Wt + (size_t)(kc + bkr) * 128 + bnc);
        __syncthreads();
#pragma unroll
        for (int k = 0; k < 8; ++k) {
            float a[8], b[8];
            *(float4*)(a)     = *(const float4*)&As[k][ty * 8];
            *(float4*)(a + 4) = *(const float4*)&As[k][ty * 8 + 4];
            *(float4*)(b)     = *(const float4*)&Bs[k][tx * 8];
            *(float4*)(b + 4) = *(const float4*)&Bs[k][tx * 8 + 4];
#pragma unroll
            for (int i = 0; i < 8; ++i)
#pragma unroll
                for (int j = 0; j < 8; ++j) acc[i][j] += a[i] * b[j];
        }
        __syncthreads();
    }
#pragma unroll
    for (int i = 0; i < 8; ++i) {
        int m = m0 + ty * 8 + i;
        if (m < NN) {
#pragma unroll
            for (int j = 0; j < 8; ++j) {
                int n = tx * 8 + j;
                float v = fmaxf(acc[i][j] * A[n] + C[n], 0.f);
                if (LAYER == 1) v += X[(size_t)m * 128 + n];
                Y[(size_t)m * 128 + n] = v;
            }
        }
    }
}

// ----------------------------------------------------------------------------
// Propagation: warp per destination node, CSR, no atomics
// hin = g_xs[k], base = g_xs[0], hout = g_xs[k+1]
// ----------------------------------------------------------------------------
__global__ void propagate_kernel(int k) {
    const size_t layer = (size_t)NN * HID;
    const float* __restrict__ hin = g_xs + (size_t)k * layer;
    float* __restrict__ hout = g_xs + (size_t)(k + 1) * layer;

    int gt = blockIdx.x * blockDim.x + threadIdx.x;
    int node = gt >> 5;
    int lane = gt & 31;
    if (node >= NN) return;
    int s = g_rowptr[node];
    int e = g_rowptr[node + 1];
    const float4* hin4 = (const float4*)hin;
    float4 acc = make_float4(0.f, 0.f, 0.f, 0.f);
    for (int i = s; i < e; ++i) {
        float2 ed = g_edge[i];             // uniform across warp -> broadcast
        int src = __float_as_int(ed.x);
        float w = ed.y;
        float4 v = hin4[(size_t)src * 32 + lane];
        acc.x += w * v.x; acc.y += w * v.y; acc.z += w * v.z; acc.w += w * v.w;
    }
    float4 b = ((const float4*)g_xs)[(size_t)node * 32 + lane];
    float4 o;
    o.x = (1.f - ALPHA) * acc.x + ALPHA * b.x;
    o.y = (1.f - ALPHA) * acc.y + ALPHA * b.y;
    o.z = (1.f - ALPHA) * acc.z + ALPHA * b.z;
    o.w = (1.f - ALPHA) * acc.w + ALPHA * b.w;
    ((float4*)hout)[(size_t)node * 32 + lane] = o;
}

// ----------------------------------------------------------------------------
// Attention weights: per node, gelu(ctx @ att1^T + b1) @ att2^T + b2 -> softmax
// ----------------------------------------------------------------------------
__global__ void attention_kernel(const float* __restrict__ att1_b,
                                 const float* __restrict__ att2_w,
                                 const float* __restrict__ att2_b) {
    __shared__ float ctx_sh[8][2 * HID];
    __shared__ float a1_sh[8][AH];
    int w = threadIdx.x >> 5;
    int lane = threadIdx.x & 31;
    int node = blockIdx.x * 8 + w;
    if (node >= NN) return;

    const float4* x0 = (const float4*)g_xs;
    const float4* xK = (const float4*)(g_xs + (size_t)KHOP * NN * HID);
    float4 v0 = x0[(size_t)node * 32 + lane];
    float4 vK = xK[(size_t)node * 32 + lane];
    *(float4*)&ctx_sh[w][lane * 4] = v0;
    *(float4*)&ctx_sh[w][HID + lane * 4] = vK;
    __syncwarp();

    // two outputs per lane: o = 2*lane, 2*lane+1
    float2 acc = make_float2(0.f, 0.f);
    const float2* W2 = (const float2*)g_attWt1;
#pragma unroll 8
    for (int c = 0; c < 2 * HID; ++c) {
        float xv = ctx_sh[w][c];
        float2 wv = W2[c * (AH / 2) + lane];
        acc.x += xv * wv.x;
        acc.y += xv * wv.y;
    }
    float z0 = acc.x + att1_b[2 * lane];
    float z1 = acc.y + att1_b[2 * lane + 1];
    // exact gelu
    float g0 = 0.5f * z0 * (1.f + erff(z0 * 0.7071067811865475f));
    float g1 = 0.5f * z1 * (1.f + erff(z1 * 0.7071067811865475f));
    a1_sh[w][2 * lane] = g0;
    a1_sh[w][2 * lane + 1] = g1;
    __syncwarp();

    float logit = -INFINITY;
    if (lane < KHOP + 1) {
        float s = att2_b[lane];
        for (int c = 0; c < AH; ++c) s += a1_sh[w][c] * att2_w[lane * AH + c];
        logit = s;
    }
    float m = logit;
#pragma unroll
    for (int off = 16; off; off >>= 1) m = fmaxf(m, __shfl_xor_sync(0xffffffffu, m, off));
    float p = (lane < KHOP + 1) ? expf(logit - m) : 0.f;
    float sum = p;
#pragma unroll
    for (int off = 16; off; off >>= 1) sum += __shfl_xor_sync(0xffffffffu, sum, off);
    if (lane < KHOP + 1) g_attw[(size_t)node * (KHOP + 1) + lane] = p / sum;
}

// ----------------------------------------------------------------------------
// Hop fusion + head MLP (BN folded) -> final output
// ----------------------------------------------------------------------------
__global__ void fused_head_kernel(const float* __restrict__ head2_b,
                                  float* __restrict__ out) {
    __shared__ float fsh[8][HID];
    __shared__ float zsh[8][HID / 2];
    int w = threadIdx.x >> 5;
    int lane = threadIdx.x & 31;
    int node = blockIdx.x * 8 + w;
    if (node >= NN) return;

    float wk[KHOP + 1];
#pragma unroll
    for (int k = 0; k <= KHOP; ++k) wk[k] = g_attw[(size_t)node * (KHOP + 1) + k];

    float4 f = make_float4(0.f, 0.f, 0.f, 0.f);
#pragma unroll
    for (int k = 0; k <= KHOP; ++k) {
        const float4* xk = (const float4*)(g_xs + (size_t)k * NN * HID);
        float4 v = xk[(size_t)node * 32 + lane];
        f.x += wk[k] * v.x; f.y += wk[k] * v.y; f.z += wk[k] * v.z; f.w += wk[k] * v.w;
    }
    *(float4*)&fsh[w][lane * 4] = f;
    __syncwarp();

    // head1: 128 -> 64, o = 2*lane, 2*lane+1
    float2 acc = make_float2(0.f, 0.f);
    const float2* W2 = (const float2*)g_h1Wt;
#pragma unroll 8
    for (int c = 0; c < HID; ++c) {
        float xv = fsh[w][c];
        float2 wv = W2[c * (HID / 4) + lane];  // HID/2 outputs -> HID/4 float2
        acc.x += xv * wv.x;
        acc.y += xv * wv.y;
    }
    zsh[w][2 * lane]     = fmaxf(acc.x * g_A3[2 * lane] + g_C3[2 * lane], 0.f);
    zsh[w][2 * lane + 1] = fmaxf(acc.y * g_A3[2 * lane + 1] + g_C3[2 * lane + 1], 0.f);
    __syncwarp();

    // head2: 64 -> 40, lanes 0..19 produce 2 outputs each
    if (lane < OUT_DIM / 2) {
        float2 acc2 = make_float2(0.f, 0.f);
        const float2* H2 = (const float2*)g_h2Wt;
#pragma unroll 8
        for (int c = 0; c < HID / 2; ++c) {
            float zv = zsh[w][c];
            float2 wv = H2[c * (OUT_DIM / 2) + lane];
            acc2.x += zv * wv.x;
            acc2.y += zv * wv.y;
        }
        acc2.x += head2_b[2 * lane];
        acc2.y += head2_b[2 * lane + 1];
        *(float2*)(out + (size_t)node * OUT_DIM + 2 * lane) = acc2;
    }
}

// ----------------------------------------------------------------------------
// Launch — no host-side symbol queries, no allocations, graph-capturable.
// ----------------------------------------------------------------------------
extern "C" void kernel_launch(void* const* d_in, const int* in_sizes, int n_in,
                              void* d_out, int out_size) {
    const float* x       = (const float*)d_in[0];
    const int*   ei      = (const int*)d_in[1];      // int32 [2, E]
    const float* ew      = (const float*)d_in[2];
    const float* lin1_w  = (const float*)d_in[3];
    const float* lin1_b  = (const float*)d_in[4];
    const float* bn1_g   = (const float*)d_in[5];
    const float* bn1_b   = (const float*)d_in[6];
    const float* bn1_m   = (const float*)d_in[7];
    const float* bn1_v   = (const float*)d_in[8];
    const float* lin2_w  = (const float*)d_in[9];
    const float* lin2_b  = (const float*)d_in[10];
    const float* bn2_g   = (const float*)d_in[11];
    const float* bn2_b   = (const float*)d_in[12];
    const float* bn2_m   = (const float*)d_in[13];
    const float* bn2_v   = (const float*)d_in[14];
    const float* att1_w  = (const float*)d_in[15];
    const float* att1_b  = (const float*)d_in[16];
    const float* att2_w  = (const float*)d_in[17];
    const float* att2_b  = (const float*)d_in[18];
    const float* head1_w = (const float*)d_in[19];
    const float* head1_b = (const float*)d_in[20];
    const float* bn3_g   = (const float*)d_in[21];
    const float* bn3_b   = (const float*)d_in[22];
    const float* bn3_m   = (const float*)d_in[23];
    const float* bn3_v   = (const float*)d_in[24];
    const float* head2_w = (const float*)d_in[25];
    const float* head2_b = (const float*)d_in[26];
    float* out = (float*)d_out;

    zero_kernel<<<(NN + 255) / 256, 256>>>();
    prep_kernel<<<(2 * HID * AH + 255) / 256, 256>>>(
        lin1_w, lin1_b, bn1_g, bn1_b, bn1_m, bn1_v,
        lin2_w, lin2_b, bn2_g, bn2_b, bn2_m, bn2_v,
        att1_w, head1_w, head1_b, bn3_g, bn3_b, bn3_m, bn3_v, head2_w);

    count_kernel<<<(EE + 255) / 256, 256>>>(ei, ew);
    scan_kernel<<<1, 1024>>>();
    fill_kernel<<<(EE + 255) / 256, 256>>>(ei, ew);

    gemm128_kernel<0><<<(NN + 127) / 128, 256>>>(x);
    gemm128_kernel<1><<<(NN + 127) / 128, 256>>>(nullptr);

    for (int k = 0; k < KHOP; ++k) {
        propagate_kernel<<<(NN * 32 + 255) / 256, 256>>>(k);
    }

    attention_kernel<<<(NN + 7) / 8, 256>>>(att1_b, att2_w, att2_b);
    fused_head_kernel<<<(NN + 7) / 8, 256>>>(head2_b, out);
}

// round 4
// speedup vs baseline: 1.0298x; 1.0298x over previous
#include <cuda_runtime.h>
#include <math.h>
#include <stdint.h>

#define NN 50000
#define EE 800000
#define IN_DIM 128
#define HID 128
#define OUT_DIM 40
#define KHOP 10
#define AH 64
#define ALPHA 0.1f
#define EPS 1e-5f

#define SCAN_B 256
#define SCAN_NB ((NN + SCAN_B - 1) / SCAN_B)   // 196

// ----------------------------------------------------------------------------
// Static device scratch
// ----------------------------------------------------------------------------
__device__ float g_xs[(KHOP + 1) * (size_t)NN * HID];   // 281.6 MB: h at every hop
__device__ float g_h1[(size_t)NN * HID];                 // stem layer-1 output
__device__ float g_wsum[NN];
__device__ int   g_deg[NN];
__device__ int   g_rowptr[NN + 1];
__device__ int   g_cursor[NN];
__device__ int   g_bsum[SCAN_NB];
__device__ int   g_boff[SCAN_NB];
__device__ float2 g_edge[EE];                            // {src bits, enorm} CSR by dest

// transposed weights + folded BN constants
__device__ float g_Wt1[IN_DIM * HID];    // [k][n]
__device__ float g_Wt2[HID * HID];       // [k][n]
__device__ float g_attWt1[2 * HID * AH]; // [c][o]
__device__ float g_h1Wt[HID * (HID / 2)];// [c][o]  128x64
__device__ float g_h2Wt[(HID / 2) * OUT_DIM]; // [c][o] 64x40
__device__ float g_A1[HID], g_C1[HID], g_A2[HID], g_C2[HID], g_A3[HID / 2], g_C3[HID / 2];

// ----------------------------------------------------------------------------
// Prep
// ----------------------------------------------------------------------------
__global__ void zero_kernel() {
    int i = blockIdx.x * blockDim.x + threadIdx.x;
    if (i < NN) { g_wsum[i] = 0.f; g_deg[i] = 0; g_cursor[i] = 0; }
}

__global__ void prep_kernel(const float* __restrict__ lin1_w, const float* __restrict__ lin1_b,
                            const float* __restrict__ bn1_g, const float* __restrict__ bn1_b,
                            const float* __restrict__ bn1_m, const float* __restrict__ bn1_v,
                            const float* __restrict__ lin2_w, const float* __restrict__ lin2_b,
                            const float* __restrict__ bn2_g, const float* __restrict__ bn2_b,
                            const float* __restrict__ bn2_m, const float* __restrict__ bn2_v,
                            const float* __restrict__ att1_w,
                            const float* __restrict__ head1_w, const float* __restrict__ head1_b,
                            const float* __restrict__ bn3_g, const float* __restrict__ bn3_b,
                            const float* __restrict__ bn3_m, const float* __restrict__ bn3_v,
                            const float* __restrict__ head2_w) {
    int tid = blockIdx.x * blockDim.x + threadIdx.x;
    if (tid < IN_DIM * HID) {
        int k = tid >> 7, n = tid & 127;
        g_Wt1[tid] = lin1_w[n * IN_DIM + k];
        g_Wt2[tid] = lin2_w[n * HID + k];
    }
    if (tid < 2 * HID * AH) {
        int c = tid >> 6, o = tid & 63;
        g_attWt1[tid] = att1_w[o * (2 * HID) + c];
    }
    if (tid < HID * (HID / 2)) {
        int c = tid >> 6, o = tid & 63;
        g_h1Wt[tid] = head1_w[o * HID + c];
    }
    if (tid < (HID / 2) * OUT_DIM) {
        int c = tid / OUT_DIM, o = tid % OUT_DIM;
        g_h2Wt[tid] = head2_w[o * (HID / 2) + c];
    }
    if (tid < HID) {
        float a1 = bn1_g[tid] * rsqrtf(bn1_v[tid] + EPS);
        g_A1[tid] = a1;
        g_C1[tid] = lin1_b[tid] * a1 + bn1_b[tid] - bn1_m[tid] * a1;
        float a2 = bn2_g[tid] * rsqrtf(bn2_v[tid] + EPS);
        g_A2[tid] = a2;
        g_C2[tid] = lin2_b[tid] * a2 + bn2_b[tid] - bn2_m[tid] * a2;
    }
    if (tid < HID / 2) {
        float a3 = bn3_g[tid] * rsqrtf(bn3_v[tid] + EPS);
        g_A3[tid] = a3;
        g_C3[tid] = head1_b[tid] * a3 + bn3_b[tid] - bn3_m[tid] * a3;
    }
}

// ----------------------------------------------------------------------------
// Graph preprocessing
// ----------------------------------------------------------------------------
__global__ void count_kernel(const int* __restrict__ ei, const float* __restrict__ ew) {
    int e = blockIdx.x * blockDim.x + threadIdx.x;
    if (e >= EE) return;
    int row = ei[e];
    int col = ei[EE + e];
    atomicAdd(&g_wsum[row], ew[e]);
    atomicAdd(&g_deg[col], 1);
}

// Phase A: per-block sums of deg
__global__ void scanA_kernel() {
    __shared__ int sh[SCAN_B];
    int t = threadIdx.x;
    int i = blockIdx.x * SCAN_B + t;
    int v = (i < NN) ? g_deg[i] : 0;
    sh[t] = v;
    __syncthreads();
#pragma unroll
    for (int off = SCAN_B / 2; off > 0; off >>= 1) {
        if (t < off) sh[t] += sh[t + off];
        __syncthreads();
    }
    if (t == 0) g_bsum[blockIdx.x] = sh[0];
}

// Phase B: exclusive scan of 196 block sums (single block)
__global__ void scanB_kernel() {
    __shared__ int sh[SCAN_NB];
    int t = threadIdx.x;
    int v = (t < SCAN_NB) ? g_bsum[t] : 0;
    if (t < SCAN_NB) sh[t] = v;
    __syncthreads();
    for (int off = 1; off < SCAN_NB; off <<= 1) {
        int x = (t < SCAN_NB && t >= off) ? sh[t - off] : 0;
        __syncthreads();
        if (t < SCAN_NB) sh[t] += x;
        __syncthreads();
    }
    if (t < SCAN_NB) g_boff[t] = sh[t] - v;  // exclusive
}

// Phase C: per-block exclusive scan + offset -> rowptr
__global__ void scanC_kernel() {
    __shared__ int sh[SCAN_B];
    int t = threadIdx.x;
    int i = blockIdx.x * SCAN_B + t;
    int v = (i < NN) ? g_deg[i] : 0;
    sh[t] = v;
    __syncthreads();
#pragma unroll
    for (int off = 1; off < SCAN_B; off <<= 1) {
        int x = (t >= off) ? sh[t - off] : 0;
        __syncthreads();
        sh[t] += x;
        __syncthreads();
    }
    if (i < NN) g_rowptr[i] = sh[t] - v + g_boff[blockIdx.x];
    if (i == NN - 1) g_rowptr[NN] = EE;
}

__global__ void fill_kernel(const int* __restrict__ ei, const float* __restrict__ ew) {
    int e = blockIdx.x * blockDim.x + threadIdx.x;
    if (e >= EE) return;
    int row = ei[e];
    int col = ei[EE + e];
    float en = ew[e] / fmaxf(g_wsum[row], 1.0f);
    int pos = g_rowptr[col] + atomicAdd(&g_cursor[col], 1);
    g_edge[pos] = make_float2(__int_as_float(row), en);
}

// ----------------------------------------------------------------------------
// Stem SGEMM
// ----------------------------------------------------------------------------
template <int LAYER>
__global__ void gemm128_kernel(const float* __restrict__ Xext) {
    const float* __restrict__ X  = (LAYER == 0) ? Xext : g_h1;
    const float* __restrict__ Wt = (LAYER == 0) ? g_Wt1 : g_Wt2;
    const float* __restrict__ A  = (LAYER == 0) ? g_A1 : g_A2;
    const float* __restrict__ C  = (LAYER == 0) ? g_C1 : g_C2;
    float* __restrict__ Y        = (LAYER == 0) ? g_h1 : g_xs;

    __shared__ float As[8][128];
    __shared__ float Bs[8][128];
    int tid = threadIdx.x;
    int m0 = blockIdx.x * 128;
    int ty = tid >> 4, tx = tid & 15;
    float acc[8][8];
#pragma unroll
    for (int i = 0; i < 8; ++i)
#pragma unroll
        for (int j = 0; j < 8; ++j) acc[i][j] = 0.f;

    int lr = tid >> 1;
    int lq = (tid & 1) * 4;
    int bkr = tid >> 5;
    int bnc = (tid & 31) * 4;

    for (int kc = 0; kc < 128; kc += 8) {
        float4 av = make_float4(0.f, 0.f, 0.f, 0.f);
        int gm = m0 + lr;
        if (gm < NN) av = *(const float4*)(X + (size_t)gm * 128 + kc + lq);
        As[lq + 0][lr] = av.x; As[lq + 1][lr] = av.y;
        As[lq + 2][lr] = av.z; As[lq + 3][lr] = av.w;
        *(float4*)&Bs[bkr][bnc] = *(const float4*)(Wt + (size_t)(kc + bkr) * 128 + bnc);
        __syncthreads();
#pragma unroll
        for (int k = 0; k < 8; ++k) {
            float a[8], b[8];
            *(float4*)(a)     = *(const float4*)&As[k][ty * 8];
            *(float4*)(a + 4) = *(const float4*)&As[k][ty * 8 + 4];
            *(float4*)(b)     = *(const float4*)&Bs[k][tx * 8];
            *(float4*)(b + 4) = *(const float4*)&Bs[k][tx * 8 + 4];
#pragma unroll
            for (int i = 0; i < 8; ++i)
#pragma unroll
                for (int j = 0; j < 8; ++j) acc[i][j] += a[i] * b[j];
        }
        __syncthreads();
    }
#pragma unroll
    for (int i = 0; i < 8; ++i) {
        int m = m0 + ty * 8 + i;
        if (m < NN) {
#pragma unroll
            for (int j = 0; j < 8; ++j) {
                int n = tx * 8 + j;
                float v = fmaxf(acc[i][j] * A[n] + C[n], 0.f);
                if (LAYER == 1) v += X[(size_t)m * 128 + n];
                Y[(size_t)m * 128 + n] = v;
            }
        }
    }
}

// ----------------------------------------------------------------------------
// Propagation: warp per node, unroll x2 with dual accumulators (2 gathers in flight)
// ----------------------------------------------------------------------------
__global__ void propagate_kernel(int k) {
    const size_t layer = (size_t)NN * HID;
    const float* __restrict__ hin = g_xs + (size_t)k * layer;
    float* __restrict__ hout = g_xs + (size_t)(k + 1) * layer;

    int gt = blockIdx.x * blockDim.x + threadIdx.x;
    int node = gt >> 5;
    int lane = gt & 31;
    if (node >= NN) return;
    int s = g_rowptr[node];
    int e = g_rowptr[node + 1];
    const float4* __restrict__ hin4 = (const float4*)hin;
    float4 acc0 = make_float4(0.f, 0.f, 0.f, 0.f);
    float4 acc1 = make_float4(0.f, 0.f, 0.f, 0.f);
    int i = s;
    for (; i + 1 < e; i += 2) {
        float2 e0 = g_edge[i];
        float2 e1 = g_edge[i + 1];
        int s0 = __float_as_int(e0.x);
        int s1 = __float_as_int(e1.x);
        float4 v0 = hin4[(size_t)s0 * 32 + lane];
        float4 v1 = hin4[(size_t)s1 * 32 + lane];
        acc0.x += e0.y * v0.x; acc0.y += e0.y * v0.y; acc0.z += e0.y * v0.z; acc0.w += e0.y * v0.w;
        acc1.x += e1.y * v1.x; acc1.y += e1.y * v1.y; acc1.z += e1.y * v1.z; acc1.w += e1.y * v1.w;
    }
    if (i < e) {
        float2 e0 = g_edge[i];
        int s0 = __float_as_int(e0.x);
        float4 v0 = hin4[(size_t)s0 * 32 + lane];
        acc0.x += e0.y * v0.x; acc0.y += e0.y * v0.y; acc0.z += e0.y * v0.z; acc0.w += e0.y * v0.w;
    }
    float4 b = ((const float4*)g_xs)[(size_t)node * 32 + lane];
    float4 o;
    o.x = (1.f - ALPHA) * (acc0.x + acc1.x) + ALPHA * b.x;
    o.y = (1.f - ALPHA) * (acc0.y + acc1.y) + ALPHA * b.y;
    o.z = (1.f - ALPHA) * (acc0.z + acc1.z) + ALPHA * b.z;
    o.w = (1.f - ALPHA) * (acc0.w + acc1.w) + ALPHA * b.w;
    ((float4*)hout)[(size_t)node * 32 + lane] = o;
}

// ----------------------------------------------------------------------------
// Merged attention + hop fusion + head MLP
// ----------------------------------------------------------------------------
__global__ void att_head_kernel(const float* __restrict__ att1_b,
                                const float* __restrict__ att2_w,
                                const float* __restrict__ att2_b,
                                const float* __restrict__ head2_b,
                                float* __restrict__ out) {
    __shared__ float ctx_sh[8][2 * HID];
    __shared__ float a1_sh[8][AH];
    __shared__ float fsh[8][HID];
    __shared__ float zsh[8][HID / 2];
    int w = threadIdx.x >> 5;
    int lane = threadIdx.x & 31;
    int node = blockIdx.x * 8 + w;
    if (node >= NN) return;

    // ---- attention ----
    const float4* x0 = (const float4*)g_xs;
    const float4* xK = (const float4*)(g_xs + (size_t)KHOP * NN * HID);
    float4 v0 = x0[(size_t)node * 32 + lane];
    float4 vK = xK[(size_t)node * 32 + lane];
    *(float4*)&ctx_sh[w][lane * 4] = v0;
    *(float4*)&ctx_sh[w][HID + lane * 4] = vK;
    __syncwarp();

    float2 acc = make_float2(0.f, 0.f);
    const float2* W2 = (const float2*)g_attWt1;
#pragma unroll 8
    for (int c = 0; c < 2 * HID; ++c) {
        float xv = ctx_sh[w][c];
        float2 wv = W2[c * (AH / 2) + lane];
        acc.x += xv * wv.x;
        acc.y += xv * wv.y;
    }
    float z0 = acc.x + att1_b[2 * lane];
    float z1 = acc.y + att1_b[2 * lane + 1];
    float g0 = 0.5f * z0 * (1.f + erff(z0 * 0.7071067811865475f));
    float g1 = 0.5f * z1 * (1.f + erff(z1 * 0.7071067811865475f));
    a1_sh[w][2 * lane] = g0;
    a1_sh[w][2 * lane + 1] = g1;
    __syncwarp();

    float logit = -INFINITY;
    if (lane < KHOP + 1) {
        float s = att2_b[lane];
#pragma unroll 8
        for (int c = 0; c < AH; ++c) s += a1_sh[w][c] * att2_w[lane * AH + c];
        logit = s;
    }
    float m = logit;
#pragma unroll
    for (int off = 16; off; off >>= 1) m = fmaxf(m, __shfl_xor_sync(0xffffffffu, m, off));
    float p = (lane < KHOP + 1) ? expf(logit - m) : 0.f;
    float sum = p;
#pragma unroll
    for (int off = 16; off; off >>= 1) sum += __shfl_xor_sync(0xffffffffu, sum, off);
    float prob = p / sum;

    float wk[KHOP + 1];
#pragma unroll
    for (int k = 0; k <= KHOP; ++k) wk[k] = __shfl_sync(0xffffffffu, prob, k);

    // ---- hop fusion ----
    float4 f = make_float4(0.f, 0.f, 0.f, 0.f);
#pragma unroll
    for (int k = 0; k <= KHOP; ++k) {
        const float4* xk = (const float4*)(g_xs + (size_t)k * NN * HID);
        float4 v = xk[(size_t)node * 32 + lane];
        f.x += wk[k] * v.x; f.y += wk[k] * v.y; f.z += wk[k] * v.z; f.w += wk[k] * v.w;
    }
    *(float4*)&fsh[w][lane * 4] = f;
    __syncwarp();

    // ---- head1: 128 -> 64 ----
    float2 acch = make_float2(0.f, 0.f);
    const float2* H1 = (const float2*)g_h1Wt;
#pragma unroll 8
    for (int c = 0; c < HID; ++c) {
        float xv = fsh[w][c];
        float2 wv = H1[c * (HID / 4) + lane];
        acch.x += xv * wv.x;
        acch.y += xv * wv.y;
    }
    zsh[w][2 * lane]     = fmaxf(acch.x * g_A3[2 * lane] + g_C3[2 * lane], 0.f);
    zsh[w][2 * lane + 1] = fmaxf(acch.y * g_A3[2 * lane + 1] + g_C3[2 * lane + 1], 0.f);
    __syncwarp();

    // ---- head2: 64 -> 40 ----
    if (lane < OUT_DIM / 2) {
        float2 acc2 = make_float2(0.f, 0.f);
        const float2* H2 = (const float2*)g_h2Wt;
#pragma unroll 8
        for (int c = 0; c < HID / 2; ++c) {
            float zv = zsh[w][c];
            float2 wv = H2[c * (OUT_DIM / 2) + lane];
            acc2.x += zv * wv.x;
            acc2.y += zv * wv.y;
        }
        acc2.x += head2_b[2 * lane];
        acc2.y += head2_b[2 * lane + 1];
        *(float2*)(out + (size_t)node * OUT_DIM + 2 * lane) = acc2;
    }
}

// ----------------------------------------------------------------------------
// Launch
// ----------------------------------------------------------------------------
extern "C" void kernel_launch(void* const* d_in, const int* in_sizes, int n_in,
                              void* d_out, int out_size) {
    const float* x       = (const float*)d_in[0];
    const int*   ei      = (const int*)d_in[1];      // int32 [2, E]
    const float* ew      = (const float*)d_in[2];
    const float* lin1_w  = (const float*)d_in[3];
    const float* lin1_b  = (const float*)d_in[4];
    const float* bn1_g   = (const float*)d_in[5];
    const float* bn1_b   = (const float*)d_in[6];
    const float* bn1_m   = (const float*)d_in[7];
    const float* bn1_v   = (const float*)d_in[8];
    const float* lin2_w  = (const float*)d_in[9];
    const float* lin2_b  = (const float*)d_in[10];
    const float* bn2_g   = (const float*)d_in[11];
    const float* bn2_b   = (const float*)d_in[12];
    const float* bn2_m   = (const float*)d_in[13];
    const float* bn2_v   = (const float*)d_in[14];
    const float* att1_w  = (const float*)d_in[15];
    const float* att1_b  = (const float*)d_in[16];
    const float* att2_w  = (const float*)d_in[17];
    const float* att2_b  = (const float*)d_in[18];
    const float* head1_w = (const float*)d_in[19];
    const float* head1_b = (const float*)d_in[20];
    const float* bn3_g   = (const float*)d_in[21];
    const float* bn3_b   = (const float*)d_in[22];
    const float* bn3_m   = (const float*)d_in[23];
    const float* bn3_v   = (const float*)d_in[24];
    const float* head2_w = (const float*)d_in[25];
    const float* head2_b = (const float*)d_in[26];
    float* out = (float*)d_out;

    zero_kernel<<<(NN + 255) / 256, 256>>>();
    prep_kernel<<<(2 * HID * AH + 255) / 256, 256>>>(
        lin1_w, lin1_b, bn1_g, bn1_b, bn1_m, bn1_v,
        lin2_w, lin2_b, bn2_g, bn2_b, bn2_m, bn2_v,
        att1_w, head1_w, head1_b, bn3_g, bn3_b, bn3_m, bn3_v, head2_w);

    count_kernel<<<(EE + 255) / 256, 256>>>(ei, ew);
    scanA_kernel<<<SCAN_NB, SCAN_B>>>();
    scanB_kernel<<<1, SCAN_NB>>>();
    scanC_kernel<<<SCAN_NB, SCAN_B>>>();
    fill_kernel<<<(EE + 255) / 256, 256>>>(ei, ew);

    gemm128_kernel<0><<<(NN + 127) / 128, 256>>>(x);
    gemm128_kernel<1><<<(NN + 127) / 128, 256>>>(nullptr);

    for (int k = 0; k < KHOP; ++k) {
        propagate_kernel<<<(NN * 32 + 255) / 256, 256>>>(k);
    }

    att_head_kernel<<<(NN + 7) / 8, 256>>>(att1_b, att2_w, att2_b, head2_b, out);
}